// round 5
// baseline (speedup 1.0000x reference)
#include <cuda_runtime.h>

#define NUM_CLS 32000
#define BATCH   4096
#define C4      (NUM_CLS / 4)   // 8000 float4 per row
#define THREADS 256
#define NWARP   (THREADS / 32)

// Per-row partial results (deterministic; no float atomics).
__device__ float g_row[BATCH];
// Completion counter; last block resets it so graph replays start clean.
__device__ unsigned int g_done;

__global__ __launch_bounds__(THREADS, 8)
void rce_fused_kernel(const float* __restrict__ inp,
                      const float* __restrict__ tgt,
                      float* __restrict__ out)
{
    const int row = blockIdx.x;
    const float4* ip = reinterpret_cast<const float4*>(inp + (size_t)row * NUM_CLS);
    const float4* tp = reinterpret_cast<const float4*>(tgt + (size_t)row * NUM_CLS);

    float s_sum = 0.f;                 // sum of x
    float e_sum = 0.f;                 // sum of exp(-x)
    unsigned cur_bits = 0xffffffffu;   // running min of target bits (t >= 0 ->
    unsigned cur_idx  = 0u;            //  float bits are order-preserving)
    float    cur_x    = 0.f;           // x value at the running argmin

    #pragma unroll 4
    for (int i = threadIdx.x; i < C4; i += THREADS) {
        const float4 x = __ldcs(ip + i);   // streamed once: evict-first
        const float4 t = __ldcs(tp + i);

        s_sum += (x.x + x.y) + (x.z + x.w);
        e_sum += (__expf(-x.x) + __expf(-x.y)) + (__expf(-x.z) + __expf(-x.w));

        const unsigned b0 = __float_as_uint(t.x);
        const unsigned b1 = __float_as_uint(t.y);
        const unsigned b2 = __float_as_uint(t.z);
        const unsigned b3 = __float_as_uint(t.w);
        // Quad-local argmin, first index wins ties; carry matching x.
        const unsigned m01 = min(b0, b1);
        const unsigned i01 = (b1 < b0) ? 1u : 0u;
        const float    x01 = (b1 < b0) ? x.y : x.x;
        const unsigned m23 = min(b2, b3);
        const unsigned i23 = (b3 < b2) ? 3u : 2u;
        const float    x23 = (b3 < b2) ? x.w : x.z;
        const bool hi = (m23 < m01);
        const unsigned m  = hi ? m23 : m01;
        const unsigned iq = hi ? i23 : i01;
        const float    xq = hi ? x23 : x01;
        // Iterations ascend per thread -> strict < keeps earlier index on tie.
        if (m < cur_bits) {
            cur_bits = m;
            cur_idx  = (unsigned)i * 4u + iq;
            cur_x    = xq;
        }
    }

    // Warp reduce. Value tie -> smaller index (global first occurrence).
    #pragma unroll
    for (int o = 16; o > 0; o >>= 1) {
        s_sum += __shfl_xor_sync(0xffffffffu, s_sum, o);
        e_sum += __shfl_xor_sync(0xffffffffu, e_sum, o);
        const unsigned ob = __shfl_xor_sync(0xffffffffu, cur_bits, o);
        const unsigned oi = __shfl_xor_sync(0xffffffffu, cur_idx,  o);
        const float    ox = __shfl_xor_sync(0xffffffffu, cur_x,    o);
        if (ob < cur_bits || (ob == cur_bits && oi < cur_idx)) {
            cur_bits = ob; cur_idx = oi; cur_x = ox;
        }
    }

    __shared__ float    sh_s[NWARP];
    __shared__ float    sh_e[NWARP];
    __shared__ unsigned sh_b[NWARP];
    __shared__ unsigned sh_i[NWARP];
    __shared__ float    sh_x[NWARP];
    __shared__ bool     sh_last;
    const int wid = threadIdx.x >> 5;
    const int lid = threadIdx.x & 31;
    if (lid == 0) { sh_s[wid] = s_sum; sh_e[wid] = e_sum;
                    sh_b[wid] = cur_bits; sh_i[wid] = cur_idx;
                    sh_x[wid] = cur_x; }
    __syncthreads();

    if (threadIdx.x == 0) {
        float S = sh_s[0], E = sh_e[0], X = sh_x[0];
        unsigned B = sh_b[0], I = sh_i[0];
        #pragma unroll
        for (int w = 1; w < NWARP; w++) {
            S += sh_s[w];
            E += sh_e[w];
            if (sh_b[w] < B || (sh_b[w] == B && sh_i[w] < I)) {
                B = sh_b[w]; I = sh_i[w]; X = sh_x[w];
            }
        }
        // r_b = S_b + (C-1)*log(E_b) - x[b, argmin_b]  (X carried in-stream)
        g_row[row] = S + (float)(NUM_CLS - 1) * logf(E) - X;

        __threadfence();
        const unsigned prev = atomicAdd(&g_done, 1u);
        sh_last = (prev == (unsigned)(BATCH - 1));
    }
    __syncthreads();

    // Last block performs the final deterministic reduction (g_row L2-hot).
    if (sh_last) {
        float s = 0.f;
        for (int i = threadIdx.x; i < BATCH; i += THREADS)
            s += __ldcg(&g_row[i]);

        #pragma unroll
        for (int o = 16; o > 0; o >>= 1)
            s += __shfl_xor_sync(0xffffffffu, s, o);

        __shared__ float sh_f[NWARP];
        if (lid == 0) sh_f[wid] = s;
        __syncthreads();

        if (threadIdx.x == 0) {
            float tot = 0.f;
            #pragma unroll
            for (int w = 0; w < NWARP; w++) tot += sh_f[w];
            // loss = (RATIO / (B*(C-1))) * sum_b r_b ; RATIO = 1.0
            out[0] = tot * (1.0f / ((float)BATCH * (float)(NUM_CLS - 1)));
            g_done = 0;   // reset for next graph replay
        }
    }
}

extern "C" void kernel_launch(void* const* d_in, const int* in_sizes, int n_in,
                              void* d_out, int out_size)
{
    const float* inp = (const float*)d_in[0];   // input  [B, C] f32
    const float* tgt = (const float*)d_in[1];   // target [B, C] f32
    float* out = (float*)d_out;                 // scalar f32

    rce_fused_kernel<<<BATCH, THREADS>>>(inp, tgt, out);
}

// round 6
// speedup vs baseline: 1.0349x; 1.0349x over previous
#include <cuda_runtime.h>

#define NUM_CLS 32000
#define BATCH   4096
#define C4      (NUM_CLS / 4)   // 8000 float4 per row
#define THREADS 512
#define NWARP   (THREADS / 32)

// Per-row partial results (deterministic; no float atomics).
__device__ float g_row[BATCH];
// Completion counter; last block resets it so graph replays start clean.
__device__ unsigned int g_done;

__global__ __launch_bounds__(THREADS, 4)
void rce_fused_kernel(const float* __restrict__ inp,
                      const float* __restrict__ tgt,
                      float* __restrict__ out)
{
    const int row = blockIdx.x;
    const float4* ip = reinterpret_cast<const float4*>(inp + (size_t)row * NUM_CLS);
    const float4* tp = reinterpret_cast<const float4*>(tgt + (size_t)row * NUM_CLS);

    float s_sum = 0.f;                 // sum of x
    float e_sum = 0.f;                 // sum of exp(-x)
    unsigned cur_bits = 0xffffffffu;   // running min of target bits (t >= 0 ->
    unsigned cur_idx  = 0u;            //  float bits are order-preserving)

    #pragma unroll 4
    for (int i = threadIdx.x; i < C4; i += THREADS) {
        const float4 x = ip[i];
        const float4 t = tp[i];

        s_sum += (x.x + x.y) + (x.z + x.w);
        e_sum += (__expf(-x.x) + __expf(-x.y)) + (__expf(-x.z) + __expf(-x.w));

        const unsigned b0 = __float_as_uint(t.x);
        const unsigned b1 = __float_as_uint(t.y);
        const unsigned b2 = __float_as_uint(t.z);
        const unsigned b3 = __float_as_uint(t.w);
        // Quad-local argmin, first index wins ties.
        const unsigned m01 = min(b0, b1);
        const unsigned i01 = (b1 < b0) ? 1u : 0u;
        const unsigned m23 = min(b2, b3);
        const unsigned i23 = (b3 < b2) ? 3u : 2u;
        const unsigned m   = min(m01, m23);
        const unsigned iq  = (m23 < m01) ? i23 : i01;
        // Iterations ascend per thread -> strict < keeps earlier index on tie.
        if (m < cur_bits) { cur_bits = m; cur_idx = (unsigned)i * 4u + iq; }
    }

    // Warp reduce. Value tie -> smaller index (global first occurrence).
    #pragma unroll
    for (int o = 16; o > 0; o >>= 1) {
        s_sum += __shfl_xor_sync(0xffffffffu, s_sum, o);
        e_sum += __shfl_xor_sync(0xffffffffu, e_sum, o);
        const unsigned ob = __shfl_xor_sync(0xffffffffu, cur_bits, o);
        const unsigned oi = __shfl_xor_sync(0xffffffffu, cur_idx,  o);
        if (ob < cur_bits || (ob == cur_bits && oi < cur_idx)) {
            cur_bits = ob; cur_idx = oi;
        }
    }

    __shared__ float    sh_s[NWARP];
    __shared__ float    sh_e[NWARP];
    __shared__ unsigned sh_b[NWARP];
    __shared__ unsigned sh_i[NWARP];
    __shared__ bool     sh_last;
    const int wid = threadIdx.x >> 5;
    const int lid = threadIdx.x & 31;
    if (lid == 0) { sh_s[wid] = s_sum; sh_e[wid] = e_sum;
                    sh_b[wid] = cur_bits; sh_i[wid] = cur_idx; }
    __syncthreads();

    if (threadIdx.x == 0) {
        float S = sh_s[0], E = sh_e[0];
        unsigned B = sh_b[0], I = sh_i[0];
        #pragma unroll
        for (int w = 1; w < NWARP; w++) {
            S += sh_s[w];
            E += sh_e[w];
            if (sh_b[w] < B || (sh_b[w] == B && sh_i[w] < I)) {
                B = sh_b[w]; I = sh_i[w];
            }
        }
        const float xi = inp[(size_t)row * NUM_CLS + I];
        // r_b = S_b + (C-1)*log(E_b) - x[b, idx]
        g_row[row] = S + (float)(NUM_CLS - 1) * logf(E) - xi;

        __threadfence();
        const unsigned prev = atomicAdd(&g_done, 1u);
        sh_last = (prev == (unsigned)(BATCH - 1));
    }
    __syncthreads();

    // Last block performs the final deterministic reduction (g_row L2-hot).
    if (sh_last) {
        float s = 0.f;
        for (int i = threadIdx.x; i < BATCH; i += THREADS)
            s += __ldcg(&g_row[i]);

        #pragma unroll
        for (int o = 16; o > 0; o >>= 1)
            s += __shfl_xor_sync(0xffffffffu, s, o);

        __shared__ float sh_f[NWARP];
        if (lid == 0) sh_f[wid] = s;
        __syncthreads();

        if (threadIdx.x == 0) {
            float tot = 0.f;
            #pragma unroll
            for (int w = 0; w < NWARP; w++) tot += sh_f[w];
            // loss = (RATIO / (B*(C-1))) * sum_b r_b ; RATIO = 1.0
            out[0] = tot * (1.0f / ((float)BATCH * (float)(NUM_CLS - 1)));
            g_done = 0;   // reset for next graph replay
        }
    }
}

extern "C" void kernel_launch(void* const* d_in, const int* in_sizes, int n_in,
                              void* d_out, int out_size)
{
    const float* inp = (const float*)d_in[0];   // input  [B, C] f32
    const float* tgt = (const float*)d_in[1];   // target [B, C] f32
    float* out = (float*)d_out;                 // scalar f32

    rce_fused_kernel<<<BATCH, THREADS>>>(inp, tgt, out);
}